// round 13
// baseline (speedup 1.0000x reference)
#include <cuda_runtime.h>
#include <cstdint>
#include <cstddef>

// ---------------------------------------------------------------------------
// Fused MoE element-wise gating, round 13: round-12 base (BT=64, 2 CTAs/SM,
// m32n32 warps, paired-k lds64) + phase-overlap staging + strength-reduced
// shared-memory addressing (all values/addresses bit-identical to round 12).
// out[b,o] = sum_e softmax_e(x@Wg+bg) * (L3(L2(L1(x)))+b3)
// B=65536, L=256, E=8, H1=128, H2=64, O=256, fp32 (tf32 mma, fp32 accum).
// ---------------------------------------------------------------------------

#define BT 64
#define LDIM 256
#define ODIM 256
#define NE 8
#define H1D 128
#define H2D 64
#define EO 2048
#define OC 128
#define NTHREADS 256

// SMEM map (float words)
#define XS_OFF 0            // x tile   [64][256] swizzled          (64 KB)
#define H1_OFF 16384        // h1 tile  [64][128] / W1,Wg,W3 staging (32 KB)
#define H2_OFF 24576        // h2 tile  [64][64]  / W2 staging       (16 KB)
#define SMEM_WORDS 28672
#define SMEM_BYTES (SMEM_WORDS * 4)     // 114688

#define W1BUF(i) (H1_OFF + (i) * 4096)   // 2 x [32k x 128n] paired-k chunks
#define W2BUF(i) (H2_OFF + (i) * 2048)   // 2 x [32k x 64n] paired-k chunks
#define WGBUF(i) (H1_OFF + (i) * 4096)   // 2 x [32k x 128n]
#define W3BUF    H1_OFF                  // 2 chunks = 8192 words (after gate)

// paired-k tf32 weight images in device scratch (word offsets)
#define W1S_OFF 0        // + e*32768 + c*4096            (c:8, N=128)
#define W2S_OFF 262144   // + e*8192  + c*2048            (c:4, N=64)
#define W3S_OFF 327680   // + e*16384 + nh*8192 + c*4096  (nh:2, c:2, N=128)
#define WGS_OFF 458752   // + e*65536 + nh*32768 + c*4096 (nh:2, c:8, N=128)
#define WS_TOTAL 983040
__device__ __align__(256) float g_ws[WS_TOTAL];

__device__ __forceinline__ uint32_t f2t(float f) {
    uint32_t u;
    asm("cvt.rna.tf32.f32 %0, %1;" : "=r"(u) : "f"(f));
    return u;
}

__device__ __forceinline__ void mma8(float c[4],
                                     uint32_t a0, uint32_t a1, uint32_t a2, uint32_t a3,
                                     uint32_t b0, uint32_t b1) {
    asm volatile(
        "mma.sync.aligned.m16n8k8.row.col.f32.tf32.tf32.f32 "
        "{%0,%1,%2,%3}, {%4,%5,%6,%7}, {%8,%9}, {%0,%1,%2,%3};"
        : "+f"(c[0]), "+f"(c[1]), "+f"(c[2]), "+f"(c[3])
        : "r"(a0), "r"(a1), "r"(a2), "r"(a3), "r"(b0), "r"(b1));
}

__device__ __forceinline__ float leaky(float v) { return v >= 0.f ? v : 0.01f * v; }

__device__ __forceinline__ void ldsm4(uint32_t a[4], uint32_t addr) {
    asm volatile("ldmatrix.sync.aligned.m8n8.x4.shared.b16 {%0,%1,%2,%3}, [%4];"
                 : "=r"(a[0]), "=r"(a[1]), "=r"(a[2]), "=r"(a[3])
                 : "r"(addr));
}

// volatile + memory clobber — must not be hoisted across CP_WAIT/__syncthreads
__device__ __forceinline__ uint2 lds64(uint32_t addr) {
    uint2 r;
    asm volatile("ld.shared.v2.u32 {%0,%1}, [%2];"
                 : "=r"(r.x), "=r"(r.y) : "r"(addr) : "memory");
    return r;
}

__device__ __forceinline__ void cpa16(uint32_t saddr, const float* g) {
    asm volatile("cp.async.cg.shared.global [%0], [%1], 16;" :: "r"(saddr), "l"(g));
}
#define CP_COMMIT() asm volatile("cp.async.commit_group;" ::: "memory")
#define CP_WAIT0()  asm volatile("cp.async.wait_group 0;" ::: "memory")

// linear cooperative copy; words must be a multiple of 1024 (256 thr x 16B)
__device__ __forceinline__ void stage_lin(uint32_t sb, int dstWord,
                                          const float* src, int words, int tid) {
    for (int i = tid * 4; i < words; i += NTHREADS * 4)
        cpa16(sb + (uint32_t)((dstWord + i) << 2), src + i);
}

// ---------------------------------------------------------------------------
// Prep: tf32-round + repack each [32k x N] weight tile into the paired-k
// image: word ((s*N+n)*4+q)*2+j = W[s*8+q+4j][n]. 256 blocks x 256 threads.
// ---------------------------------------------------------------------------
__global__ void prep_weights(const float* __restrict__ W1, const float* __restrict__ W2,
                             const float* __restrict__ W3, const float* __restrict__ Wg) {
    __shared__ float t[32][129];
    const int j = blockIdx.x;
    const int tid = threadIdx.x;

    const float* src;
    int stride, N, lg;
    long dst;
    if (j < 64) {                     // W1 [8e][256k][128n]: tile (e, c:8)
        const int e = j >> 3, c = j & 7;
        src = W1 + e * 32768 + c * 32 * 128; stride = 128; N = 128; lg = 7;
        dst = W1S_OFF + e * 32768 + c * 4096;
    } else if (j < 96) {              // W2 [8e][128k][64n]: tile (e, c:4)
        const int t2 = j - 64, e = t2 >> 2, c = t2 & 3;
        src = W2 + e * 8192 + c * 32 * 64; stride = 64; N = 64; lg = 6;
        dst = W2S_OFF + e * 8192 + c * 2048;
    } else if (j < 128) {             // W3 [8e][64k][256n]: tile (e, nh:2, c:2)
        const int t3 = j - 96, e = t3 >> 2, nh = (t3 >> 1) & 1, c = t3 & 1;
        src = W3 + e * 16384 + c * 32 * 256 + nh * 128; stride = 256; N = 128; lg = 7;
        dst = W3S_OFF + e * 16384 + nh * 8192 + c * 4096;
    } else {                          // Wg [256k][2048n]: tile (e, nh:2, c:8)
        const int t4 = j - 128, e = t4 >> 4, nh = (t4 >> 3) & 1, c = t4 & 7;
        src = Wg + c * 32 * EO + e * 256 + nh * 128; stride = EO; N = 128; lg = 7;
        dst = WGS_OFF + e * 65536 + nh * 32768 + c * 4096;
    }

    for (int i = tid; i < 32 * N; i += 256) {
        const int k = i >> lg, n = i & (N - 1);
        t[k][n] = __uint_as_float(f2t(src[(size_t)k * stride + n]));
    }
    __syncthreads();
    for (int idx = tid; idx < 32 * N; idx += 256) {
        const int jj = idx & 1;
        const int q  = (idx >> 1) & 3;
        const int n  = (idx >> 3) & (N - 1);
        const int s  = idx >> (3 + lg);
        g_ws[dst + idx] = t[s * 8 + q + 4 * jj][n];
    }
}

__global__ void __launch_bounds__(NTHREADS, 2)
moe_fused_kernel(const float* __restrict__ x,
                 const float* __restrict__ b1, const float* __restrict__ b2,
                 const float* __restrict__ b3, const float* __restrict__ bg,
                 float* __restrict__ out) {
    extern __shared__ float sm[];
    const uint32_t sb = (uint32_t)__cvta_generic_to_shared(sm);

    const int tid  = threadIdx.x;
    const int w    = tid >> 5;
    const int lane = tid & 31;
    const int g    = lane >> 2;    // 0..7
    const int tq   = lane & 3;     // 0..3
    const int mq   = w & 1;        // m-warp: rows mq*32 .. +31 (2 m16 tiles)
    const int ng   = w >> 1;       // n-group (0..3): 32 cols

    const int btile = blockIdx.x >> 1;
    const int octa  = (blockIdx.x & 1) * OC;
    const int row0  = btile * BT;

    // ldmatrix per-lane addressing
    const int lbase = (((lane >> 3) & 1) << 3) + (lane & 7);
    const int lrow0 = mq * 32 + lbase;
    const int lrow1 = lrow0 + 16;
    const int lsw   = (lrow0 & 7) << 2;
    const int lcb   = (lane >> 4) << 2;
    const uint32_t xsRow0 = sb + (uint32_t)((XS_OFF + lrow0 * LDIM) << 2);
    const uint32_t xsRow1 = sb + (uint32_t)((XS_OFF + lrow1 * LDIM) << 2);
    const uint32_t h1Row0 = sb + (uint32_t)((H1_OFF + lrow0 * H1D) << 2);
    const uint32_t h1Row1 = sb + (uint32_t)((H1_OFF + lrow1 * H1D) << 2);
    const uint32_t h2Row0 = sb + (uint32_t)((H2_OFF + lrow0 * H2D) << 2);
    const uint32_t h2Row1 = sb + (uint32_t)((H2_OFF + lrow1 * H2D) << 2);

    const int nb1 = ng * 32 + g;   // N=128 GEMMs (L1, gate, L3)
    const int nb2 = ng * 16 + g;   // N=64 (L2)
    const int bq  = tq * 2;        // pair word offset

    // Strength-reduced per-warp address constants (identical final addresses:
    // chunk bases have bits>=5 only, the swizzle XOR touches bits 2..4 which
    // live entirely in (s<<3)+lcb and lsw, so the XOR distributes out).
    uint32_t offs[4];
#pragma unroll
    for (int s = 0; s < 4; s++)
        offs[s] = (uint32_t)(((((s << 3) + lcb) ^ lsw)) << 2);
    const uint32_t boffB  = (uint32_t)(((nb1 << 3) + bq) << 2);
    const uint32_t boffB2 = (uint32_t)(((nb2 << 3) + bq) << 2);

    // ---- load x tile -> tf32 -> swizzled SMEM ----
    for (int i = tid; i < BT * (LDIM / 4); i += NTHREADS) {
        const int r  = i >> 6;
        const int c4 = i & 63;
        float4 v = reinterpret_cast<const float4*>(x + (size_t)(row0 + r) * LDIM)[c4];
        v.x = __uint_as_float(f2t(v.x)); v.y = __uint_as_float(f2t(v.y));
        v.z = __uint_as_float(f2t(v.z)); v.w = __uint_as_float(f2t(v.w));
        const int col = c4 * 4;
        *reinterpret_cast<float4*>(sm + XS_OFF + r * LDIM + (col ^ ((r & 7) << 2))) = v;
    }

    float acc[8][4], ssum[8][4];
#pragma unroll
    for (int i = 0; i < 8; i++)
#pragma unroll
        for (int jj = 0; jj < 4; jj++) { acc[i][jj] = 0.f; ssum[i][jj] = 0.f; }

    for (int e = 0; e < NE; e++) {
        const float* w1i = g_ws + W1S_OFF + e * 32768;
        const float* w2i = g_ws + W2S_OFF + e * 8192;
        const float* w3i = g_ws + W3S_OFF + e * 16384 + (octa ? 8192 : 0);
        const float* wgi = g_ws + WGS_OFF + e * 65536 + (octa ? 32768 : 0);

        __syncthreads();   // S0: h1/h2 regions free (prev expert fully folded)

        // prestage BOTH W2 chunks (h2 region is idle through the whole L1
        // phase) so the L2 phase never waits on a cold copy
        stage_lin(sb, W2BUF(0), w2i, 2048, tid);
        stage_lin(sb, W2BUF(1), w2i + 2048, 2048, tid);
        CP_COMMIT();

        // ================= layer 1: h1 = leaky(x @ W1_e + b1_e) ================
        stage_lin(sb, W1BUF(0), w1i, 4096, tid);
        CP_COMMIT();

        float c1[2][4][4];
#pragma unroll
        for (int t = 0; t < 2; t++)
#pragma unroll
            for (int i = 0; i < 4; i++)
#pragma unroll
                for (int jj = 0; jj < 4; jj++) c1[t][i][jj] = 0.f;

        for (int c = 0; c < 8; c++) {
            CP_WAIT0();
            __syncthreads();
            if (c < 7) {
                stage_lin(sb, W1BUF((c + 1) & 1), w1i + (c + 1) * 4096, 4096, tid);
                CP_COMMIT();
            }
            const uint32_t wb1 = sb + (uint32_t)(W1BUF(c & 1) << 2) + boffB;
            const uint32_t xc0 = xsRow0 + (uint32_t)(c << 7);
            const uint32_t xc1 = xsRow1 + (uint32_t)(c << 7);
#pragma unroll
            for (int s = 0; s < 4; s++) {
                uint32_t a0[4], a1[4];
                ldsm4(a0, xc0 + offs[s]);
                ldsm4(a1, xc1 + offs[s]);
                uint2 bp[4];
#pragma unroll
                for (int nt = 0; nt < 4; nt++)
                    bp[nt] = lds64(wb1 + (uint32_t)(((s * 128 + nt * 8) << 3) << 2));
#pragma unroll
                for (int nt = 0; nt < 4; nt++) {
                    mma8(c1[0][nt], a0[0], a0[1], a0[2], a0[3], bp[nt].x, bp[nt].y);
                    mma8(c1[1][nt], a1[0], a1[1], a1[2], a1[3], bp[nt].x, bp[nt].y);
                }
            }
        }
        __syncthreads();   // all warps done reading W1 bufs (h1 region)

        // h1 epilogue -> h1 region
        {
#pragma unroll
            for (int t = 0; t < 2; t++) {
                const int ar = mq * 32 + t * 16 + g;
                const int sw = (ar & 7) << 2;
#pragma unroll
                for (int nt = 0; nt < 4; nt++) {
                    const int colb = ng * 32 + nt * 8 + 2 * tq;
                    const float bb0 = b1[e * H1D + colb];
                    const float bb1 = b1[e * H1D + colb + 1];
                    float2 v0, v1;
                    v0.x = __uint_as_float(f2t(leaky(c1[t][nt][0] + bb0)));
                    v0.y = __uint_as_float(f2t(leaky(c1[t][nt][1] + bb1)));
                    v1.x = __uint_as_float(f2t(leaky(c1[t][nt][2] + bb0)));
                    v1.y = __uint_as_float(f2t(leaky(c1[t][nt][3] + bb1)));
                    *reinterpret_cast<float2*>(sm + H1_OFF + ar * H1D + (colb ^ sw))       = v0;
                    *reinterpret_cast<float2*>(sm + H1_OFF + (ar + 8) * H1D + (colb ^ sw)) = v1;
                }
            }
        }
        __syncthreads();   // h1 visible

        // ================= layer 2: h2 = leaky(h1 @ W2_e + b2_e) ===============
        // chunks 0,1 already resident (prestaged); stream 2,3 through the bufs
        float c2[2][2][4];
#pragma unroll
        for (int t = 0; t < 2; t++)
#pragma unroll
            for (int i = 0; i < 2; i++)
#pragma unroll
                for (int jj = 0; jj < 4; jj++) c2[t][i][jj] = 0.f;

        for (int c = 0; c < 4; c++) {
            CP_WAIT0();
            __syncthreads();
            if (c >= 1 && c <= 2) {   // buf((c+1)&1) free: its chunk consumed at c-1
                stage_lin(sb, W2BUF((c + 1) & 1), w2i + (c + 1) * 2048, 2048, tid);
                CP_COMMIT();
            }
            const uint32_t wb2 = sb + (uint32_t)(W2BUF(c & 1) << 2) + boffB2;
            const uint32_t hc0 = h1Row0 + (uint32_t)(c << 7);
            const uint32_t hc1 = h1Row1 + (uint32_t)(c << 7);
#pragma unroll
            for (int s = 0; s < 4; s++) {
                uint32_t a0[4], a1[4];
                ldsm4(a0, hc0 + offs[s]);
                ldsm4(a1, hc1 + offs[s]);
                uint2 bp[2];
#pragma unroll
                for (int nt = 0; nt < 2; nt++)
                    bp[nt] = lds64(wb2 + (uint32_t)(((s * 64 + nt * 8) << 3) << 2));
#pragma unroll
                for (int nt = 0; nt < 2; nt++) {
                    mma8(c2[0][nt], a0[0], a0[1], a0[2], a0[3], bp[nt].x, bp[nt].y);
                    mma8(c2[1][nt], a1[0], a1[1], a1[2], a1[3], bp[nt].x, bp[nt].y);
                }
            }
        }
        __syncthreads();   // done reading W2 bufs (h2 region) + h1 data

        // Wg chunk 0 into h1 region (freed by the sync above) — overlaps the
        // h2 epilogue below
        stage_lin(sb, WGBUF(0), wgi, 4096, tid);
        CP_COMMIT();

        // h2 epilogue -> h2 region (overwrites W2 staging)
        {
#pragma unroll
            for (int t = 0; t < 2; t++) {
                const int ar = mq * 32 + t * 16 + g;
                const int sw = (ar & 7) << 2;
#pragma unroll
                for (int nt = 0; nt < 2; nt++) {
                    const int colb = ng * 16 + nt * 8 + 2 * tq;
                    const float bb0 = b2[e * H2D + colb];
                    const float bb1 = b2[e * H2D + colb + 1];
                    float2 v0, v1;
                    v0.x = __uint_as_float(f2t(leaky(c2[t][nt][0] + bb0)));
                    v0.y = __uint_as_float(f2t(leaky(c2[t][nt][1] + bb1)));
                    v1.x = __uint_as_float(f2t(leaky(c2[t][nt][2] + bb0)));
                    v1.y = __uint_as_float(f2t(leaky(c2[t][nt][3] + bb1)));
                    *reinterpret_cast<float2*>(sm + H2_OFF + ar * H2D + (colb ^ sw))       = v0;
                    *reinterpret_cast<float2*>(sm + H2_OFF + (ar + 8) * H2D + (colb ^ sw)) = v1;
                }
            }
        }

        // ====== gate GEMM (Wg chunks through h1 region) ========================
        float cg[2][4][4];
#pragma unroll
        for (int t = 0; t < 2; t++)
#pragma unroll
            for (int i = 0; i < 4; i++)
#pragma unroll
                for (int jj = 0; jj < 4; jj++) cg[t][i][jj] = 0.f;

        for (int c = 0; c < 8; c++) {
            CP_WAIT0();
            __syncthreads();
            if (c < 7) {
                stage_lin(sb, WGBUF((c + 1) & 1), wgi + (c + 1) * 4096, 4096, tid);
                CP_COMMIT();
            } else {
                // WGBUF(0) free (last read at c==6, fenced by this iter's sync):
                // start W3 chunk 0 while computing the final gate chunk
                stage_lin(sb, W3BUF, w3i, 4096, tid);
                CP_COMMIT();
            }
            const uint32_t wbg = sb + (uint32_t)(WGBUF(c & 1) << 2) + boffB;
            const uint32_t xc0 = xsRow0 + (uint32_t)(c << 7);
            const uint32_t xc1 = xsRow1 + (uint32_t)(c << 7);
#pragma unroll
            for (int s = 0; s < 4; s++) {
                uint32_t a0[4], a1[4];
                ldsm4(a0, xc0 + offs[s]);
                ldsm4(a1, xc1 + offs[s]);
                uint2 bp[4];
#pragma unroll
                for (int nt = 0; nt < 4; nt++)
                    bp[nt] = lds64(wbg + (uint32_t)(((s * 128 + nt * 8) << 3) << 2));
#pragma unroll
                for (int nt = 0; nt < 4; nt++) {
                    mma8(cg[0][nt], a0[0], a0[1], a0[2], a0[3], bp[nt].x, bp[nt].y);
                    mma8(cg[1][nt], a1[0], a1[1], a1[2], a1[3], bp[nt].x, bp[nt].y);
                }
            }
        }
        __syncthreads();   // all warps done reading WGBUF(1)

        // W3 chunk 1 into the second half (W3 chunk 0 already in flight)
        stage_lin(sb, W3BUF + 4096, w3i + 4096, 4096, tid);
        CP_COMMIT();
        CP_WAIT0();
        __syncthreads();   // W3 fully visible

        // ====== layer 3 + fold, per m-tile =====================================
        const uint32_t w3a = sb + (uint32_t)(W3BUF << 2) + boffB;
        const uint32_t w3b = w3a + (uint32_t)(4096 << 2);
#pragma unroll 1
        for (int t = 0; t < 2; t++) {
            float co[4][4];
#pragma unroll
            for (int i = 0; i < 4; i++)
#pragma unroll
                for (int jj = 0; jj < 4; jj++) co[i][jj] = 0.f;

            const uint32_t hRow = t ? h2Row1 : h2Row0;
#pragma unroll
            for (int ks = 0; ks < 8; ks++) {
                uint32_t a[4];
                ldsm4(a, hRow + (uint32_t)((ks >> 2) << 7) + offs[ks & 3]);
                const uint32_t wb3 = (ks < 4) ? w3a : w3b;
                const int s3 = ks & 3;
                uint2 bp[4];
#pragma unroll
                for (int nt = 0; nt < 4; nt++)
                    bp[nt] = lds64(wb3 + (uint32_t)(((s3 * 128 + nt * 8) << 3) << 2));
#pragma unroll
                for (int nt = 0; nt < 4; nt++)
                    mma8(co[nt], a[0], a[1], a[2], a[3], bp[nt].x, bp[nt].y);
            }
            // fold: acc += exp(gate)*(o+b3); ssum += exp(gate)
#pragma unroll
            for (int nt = 0; nt < 4; nt++) {
                const int colc = octa + ng * 32 + nt * 8 + 2 * tq;
                const float bg0 = bg[e * ODIM + colc];
                const float bg1 = bg[e * ODIM + colc + 1];
                const float b30 = b3[e * ODIM + colc];
                const float b31 = b3[e * ODIM + colc + 1];
                const int ai = t * 4 + nt;
                float p;
                p = __expf(cg[t][nt][0] + bg0); acc[ai][0] += p * (co[nt][0] + b30); ssum[ai][0] += p;
                p = __expf(cg[t][nt][1] + bg1); acc[ai][1] += p * (co[nt][1] + b31); ssum[ai][1] += p;
                p = __expf(cg[t][nt][2] + bg0); acc[ai][2] += p * (co[nt][2] + b30); ssum[ai][2] += p;
                p = __expf(cg[t][nt][3] + bg1); acc[ai][3] += p * (co[nt][3] + b31); ssum[ai][3] += p;
            }
        }
        // expert-top S0 guards h1(W3)/h2 region reuse
    }

    // ---- epilogue: out = acc / ssum ----
#pragma unroll
    for (int ai = 0; ai < 8; ai++) {
        const int t = ai >> 2, nt = ai & 3;
        const int colc = octa + ng * 32 + nt * 8 + 2 * tq;
        const int ar = mq * 32 + t * 16 + g;
        const size_t r0 = (size_t)(row0 + ar) * ODIM;
        const size_t r1 = (size_t)(row0 + ar + 8) * ODIM;
        float2 v0 = make_float2(acc[ai][0] / ssum[ai][0], acc[ai][1] / ssum[ai][1]);
        float2 v1 = make_float2(acc[ai][2] / ssum[ai][2], acc[ai][3] / ssum[ai][3]);
        *reinterpret_cast<float2*>(out + r0 + colc) = v0;
        *reinterpret_cast<float2*>(out + r1 + colc) = v1;
    }
}

extern "C" void kernel_launch(void* const* d_in, const int* in_sizes, int n_in,
                              void* d_out, int out_size) {
    const float* x  = (const float*)d_in[0];
    const float* W1 = (const float*)d_in[1];
    const float* b1 = (const float*)d_in[2];
    const float* W2 = (const float*)d_in[3];
    const float* b2 = (const float*)d_in[4];
    const float* W3 = (const float*)d_in[5];
    const float* b3 = (const float*)d_in[6];
    const float* Wg = (const float*)d_in[7];
    const float* bg = (const float*)d_in[8];
    float* out = (float*)d_out;
    (void)n_in; (void)out_size;

    const int B  = in_sizes[0] / LDIM;       // 65536
    const int nb = (B / BT) * 2;             // 2048 CTAs

    prep_weights<<<256, 256>>>(W1, W2, W3, Wg);

    cudaFuncSetAttribute(moe_fused_kernel,
                         cudaFuncAttributeMaxDynamicSharedMemorySize, SMEM_BYTES);
    moe_fused_kernel<<<nb, NTHREADS, SMEM_BYTES>>>(x, b1, b2, b3, bg, out);
}

// round 14
// speedup vs baseline: 1.5930x; 1.5930x over previous
#include <cuda_runtime.h>
#include <cuda_fp16.h>
#include <cstdint>
#include <cstddef>

// ---------------------------------------------------------------------------
// Fused MoE element-wise gating, round 14: fp16 m16n8k16 mma (11-bit mantissa,
// same as tf32; fp32 accumulate). Halves SMEM bytes AND mma instruction count
// vs the tf32 k8 kernel. Structure (BT=64, 2 CTAs/SM, m32n32 warps, paired
// B images, phase overlap) identical to round 13.
// out[b,o] = sum_e softmax_e(x@Wg+bg) * (L3(L2(L1(x)))+b3)
// B=65536, L=256, E=8, H1=128, H2=64, O=256.
// ---------------------------------------------------------------------------

#define BT 64
#define LDIM 256
#define ODIM 256
#define NE 8
#define H1D 128
#define H2D 64
#define EO 2048
#define OC 128
#define NTHREADS 256

// SMEM byte map
#define XS_B 0              // x tile  [64][256] fp16 swizzled      (32 KB)
#define H1_B 32768          // h1 tile [64][128] fp16 / W1,Wg,W3 st (16 KB)
#define H2_B 49152          // h2 tile [64][64]  fp16 / W2 staging  ( 8 KB)
#define SMEM_BYTES 57344

#define W1BUF(i) (H1_B + (i) * 8192)   // 2 x [32k x 128n] fp16 chunks (8KB)
#define W2BUF(i) (H2_B + (i) * 4096)   // 2 x [32k x 64n]  fp16 chunks (4KB)
#define WGBUF(i) (H1_B + (i) * 8192)
#define W3BUF    H1_B                  // 2 chunks = 16 KB (after gate)

// fp16 paired-k weight images in device scratch (offsets in halfs, ~1.9 MB)
// chunk image: half ((s*N+n)*4+tq)*4+j = W[s*16 + 2tq + (j&1) + 8*(j>>1)][n]
#define W1S_OFF 0        // + e*32768 + c*4096            (c:8, N=128)
#define W2S_OFF 262144   // + e*8192  + c*2048            (c:4, N=64)
#define W3S_OFF 327680   // + e*16384 + nh*8192 + c*4096  (nh:2, c:2, N=128)
#define WGS_OFF 458752   // + e*65536 + nh*32768 + c*4096 (nh:2, c:8, N=128)
#define WS_TOTAL 983040
__device__ __align__(256) __half g_ws[WS_TOTAL];

__device__ __forceinline__ void mma16(float c[4],
                                      uint32_t a0, uint32_t a1, uint32_t a2, uint32_t a3,
                                      uint32_t b0, uint32_t b1) {
    asm volatile(
        "mma.sync.aligned.m16n8k16.row.col.f32.f16.f16.f32 "
        "{%0,%1,%2,%3}, {%4,%5,%6,%7}, {%8,%9}, {%0,%1,%2,%3};"
        : "+f"(c[0]), "+f"(c[1]), "+f"(c[2]), "+f"(c[3])
        : "r"(a0), "r"(a1), "r"(a2), "r"(a3), "r"(b0), "r"(b1));
}

__device__ __forceinline__ float leaky(float v) { return v >= 0.f ? v : 0.01f * v; }

__device__ __forceinline__ void ldsm4(uint32_t a[4], uint32_t addr) {
    asm volatile("ldmatrix.sync.aligned.m8n8.x4.shared.b16 {%0,%1,%2,%3}, [%4];"
                 : "=r"(a[0]), "=r"(a[1]), "=r"(a[2]), "=r"(a[3])
                 : "r"(addr));
}

// volatile + memory clobber — must not be hoisted across CP_WAIT/__syncthreads
__device__ __forceinline__ uint2 lds64(uint32_t addr) {
    uint2 r;
    asm volatile("ld.shared.v2.u32 {%0,%1}, [%2];"
                 : "=r"(r.x), "=r"(r.y) : "r"(addr) : "memory");
    return r;
}

__device__ __forceinline__ void cpa16(uint32_t saddr, const void* g) {
    asm volatile("cp.async.cg.shared.global [%0], [%1], 16;" :: "r"(saddr), "l"(g));
}
#define CP_COMMIT() asm volatile("cp.async.commit_group;" ::: "memory")
#define CP_WAIT0()  asm volatile("cp.async.wait_group 0;" ::: "memory")

// linear cooperative copy of fp16 data (halfs multiple of 2048)
__device__ __forceinline__ void stage_lin(uint32_t sb, int dstByte,
                                          const __half* src, int halfs, int tid) {
    for (int i = tid * 8; i < halfs; i += NTHREADS * 8)
        cpa16(sb + (uint32_t)dstByte + (uint32_t)(i * 2), src + i);
}

__device__ __forceinline__ uint32_t h2u(__half2 h) {
    return *reinterpret_cast<uint32_t*>(&h);
}

// ---------------------------------------------------------------------------
// Prep: fp16-convert + repack each [32k x N] weight tile into the paired-k
// fp16 image. 256 blocks x 256 threads (tiling identical to round 13).
// ---------------------------------------------------------------------------
__global__ void prep_weights(const float* __restrict__ W1, const float* __restrict__ W2,
                             const float* __restrict__ W3, const float* __restrict__ Wg) {
    __shared__ float t[32][129];
    const int j = blockIdx.x;
    const int tid = threadIdx.x;

    const float* src;
    int stride, N, lg;
    long dst;
    if (j < 64) {                     // W1 [8e][256k][128n]: tile (e, c:8)
        const int e = j >> 3, c = j & 7;
        src = W1 + e * 32768 + c * 32 * 128; stride = 128; N = 128; lg = 7;
        dst = W1S_OFF + e * 32768 + c * 4096;
    } else if (j < 96) {              // W2 [8e][128k][64n]: tile (e, c:4)
        const int t2 = j - 64, e = t2 >> 2, c = t2 & 3;
        src = W2 + e * 8192 + c * 32 * 64; stride = 64; N = 64; lg = 6;
        dst = W2S_OFF + e * 8192 + c * 2048;
    } else if (j < 128) {             // W3 [8e][64k][256n]: tile (e, nh:2, c:2)
        const int t3 = j - 96, e = t3 >> 2, nh = (t3 >> 1) & 1, c = t3 & 1;
        src = W3 + e * 16384 + c * 32 * 256 + nh * 128; stride = 256; N = 128; lg = 7;
        dst = W3S_OFF + e * 16384 + nh * 8192 + c * 4096;
    } else {                          // Wg [256k][2048n]: tile (e, nh:2, c:8)
        const int t4 = j - 128, e = t4 >> 4, nh = (t4 >> 3) & 1, c = t4 & 7;
        src = Wg + c * 32 * EO + e * 256 + nh * 128; stride = EO; N = 128; lg = 7;
        dst = WGS_OFF + e * 65536 + nh * 32768 + c * 4096;
    }

    for (int i = tid; i < 32 * N; i += 256) {
        const int k = i >> lg, n = i & (N - 1);
        t[k][n] = src[(size_t)k * stride + n];
    }
    __syncthreads();
    for (int idx = tid; idx < 32 * N; idx += 256) {
        const int jj = idx & 3;
        const int tq = (idx >> 2) & 3;
        const int n  = (idx >> 4) & (N - 1);
        const int s  = idx >> (4 + lg);
        const int k  = s * 16 + 2 * tq + (jj & 1) + ((jj >> 1) << 3);
        g_ws[dst + idx] = __float2half_rn(t[k][n]);
    }
}

__global__ void __launch_bounds__(NTHREADS, 2)
moe_fused_kernel(const float* __restrict__ x,
                 const float* __restrict__ b1, const float* __restrict__ b2,
                 const float* __restrict__ b3, const float* __restrict__ bg,
                 float* __restrict__ out) {
    extern __shared__ float sm[];
    char* smc = reinterpret_cast<char*>(sm);
    const uint32_t sb = (uint32_t)__cvta_generic_to_shared(sm);

    const int tid  = threadIdx.x;
    const int w    = tid >> 5;
    const int lane = tid & 31;
    const int g    = lane >> 2;    // 0..7
    const int tq   = lane & 3;     // 0..3
    const int mq   = w & 1;        // m-warp: rows mq*32 .. +31
    const int ng   = w >> 1;       // n-group (0..3): 32 cols

    const int btile = blockIdx.x >> 1;
    const int octa  = (blockIdx.x & 1) * OC;
    const int row0  = btile * BT;

    // ldmatrix per-lane addressing (fp16 rows; 16B granules, gran ^ (row&7))
    const int lbase = (((lane >> 3) & 1) << 3) + (lane & 7);
    const int lrow0 = mq * 32 + lbase;
    const int lrow1 = lrow0 + 16;               // same low 3 bits
    const int rm    = lrow0 & 7;
    const int hi    = lane >> 4;                // 0/1: k-halves of the tile
    const uint32_t xRow0  = sb + XS_B + (uint32_t)(lrow0 * 512);
    const uint32_t xRow1  = sb + XS_B + (uint32_t)(lrow1 * 512);
    const uint32_t h1Row0 = sb + H1_B + (uint32_t)(lrow0 * 256);
    const uint32_t h1Row1 = sb + H1_B + (uint32_t)(lrow1 * 256);
    const uint32_t h2Row0 = sb + H2_B + (uint32_t)(lrow0 * 128);
    const uint32_t h2Row1 = sb + H2_B + (uint32_t)(lrow1 * 128);

    // B fragment byte offsets inside a chunk image: n*32 + tq*8
    const int nb1 = ng * 32 + g;
    const int nb2 = ng * 16 + g;
    const uint32_t boffB  = (uint32_t)(nb1 * 32 + tq * 8);
    const uint32_t boffB2 = (uint32_t)(nb2 * 32 + tq * 8);

    // ---- load x tile -> fp16 -> swizzled SMEM (16B granules) ----
    for (int i = tid; i < BT * 32; i += NTHREADS) {
        const int r = i >> 5, gr = i & 31;
        const float4* xr = reinterpret_cast<const float4*>(x + (size_t)(row0 + r) * LDIM);
        const float4 a = xr[gr * 2];
        const float4 b = xr[gr * 2 + 1];
        uint4 u;
        u.x = h2u(__floats2half2_rn(a.x, a.y));
        u.y = h2u(__floats2half2_rn(a.z, a.w));
        u.z = h2u(__floats2half2_rn(b.x, b.y));
        u.w = h2u(__floats2half2_rn(b.z, b.w));
        *reinterpret_cast<uint4*>(smc + XS_B + r * 512 + ((gr ^ (r & 7)) << 4)) = u;
    }

    float acc[8][4], ssum[8][4];
#pragma unroll
    for (int i = 0; i < 8; i++)
#pragma unroll
        for (int jj = 0; jj < 4; jj++) { acc[i][jj] = 0.f; ssum[i][jj] = 0.f; }

    for (int e = 0; e < NE; e++) {
        const __half* w1i = g_ws + W1S_OFF + e * 32768;
        const __half* w2i = g_ws + W2S_OFF + e * 8192;
        const __half* w3i = g_ws + W3S_OFF + e * 16384 + (octa ? 8192 : 0);
        const __half* wgi = g_ws + WGS_OFF + e * 65536 + (octa ? 32768 : 0);

        __syncthreads();   // S0: h1/h2 regions free

        // prestage both W2 chunks 0,1 (h2 region idle through L1 phase)
        stage_lin(sb, W2BUF(0), w2i, 2048, tid);
        stage_lin(sb, W2BUF(1), w2i + 2048, 2048, tid);
        CP_COMMIT();

        // ================= layer 1: h1 = leaky(x @ W1_e + b1_e) ================
        stage_lin(sb, W1BUF(0), w1i, 4096, tid);
        CP_COMMIT();

        float c1[2][4][4];
#pragma unroll
        for (int t = 0; t < 2; t++)
#pragma unroll
            for (int i = 0; i < 4; i++)
#pragma unroll
                for (int jj = 0; jj < 4; jj++) c1[t][i][jj] = 0.f;

        for (int c = 0; c < 8; c++) {
            CP_WAIT0();
            __syncthreads();
            if (c < 7) {
                stage_lin(sb, W1BUF((c + 1) & 1), w1i + (c + 1) * 4096, 4096, tid);
                CP_COMMIT();
            }
            const uint32_t wb1 = sb + (uint32_t)W1BUF(c & 1) + boffB;
#pragma unroll
            for (int s = 0; s < 2; s++) {
                const uint32_t sw = (uint32_t)((((c << 2) + (s << 1) + hi) ^ rm) << 4);
                uint32_t a0[4], a1[4];
                ldsm4(a0, xRow0 + sw);
                ldsm4(a1, xRow1 + sw);
                uint2 bp[4];
#pragma unroll
                for (int nt = 0; nt < 4; nt++)
                    bp[nt] = lds64(wb1 + (uint32_t)(s * 4096 + nt * 256));
#pragma unroll
                for (int nt = 0; nt < 4; nt++) {
                    mma16(c1[0][nt], a0[0], a0[1], a0[2], a0[3], bp[nt].x, bp[nt].y);
                    mma16(c1[1][nt], a1[0], a1[1], a1[2], a1[3], bp[nt].x, bp[nt].y);
                }
            }
        }
        __syncthreads();   // all warps done reading W1 bufs (h1 region)

        // h1 epilogue: bias + leaky -> fp16 -> h1 region (swizzled)
        {
#pragma unroll
            for (int t = 0; t < 2; t++) {
                const int ar = mq * 32 + t * 16 + g;
                const int arm = ar & 7;
#pragma unroll
                for (int nt = 0; nt < 4; nt++) {
                    const int colb = ng * 32 + nt * 8 + 2 * tq;
                    const float bb0 = b1[e * H1D + colb];
                    const float bb1 = b1[e * H1D + colb + 1];
                    const int gr = colb >> 3;
                    const int bo = (colb & 7) * 2;
                    *reinterpret_cast<__half2*>(smc + H1_B + ar * 256 +
                        (((gr) ^ arm) << 4) + bo) =
                        __floats2half2_rn(leaky(c1[t][nt][0] + bb0), leaky(c1[t][nt][1] + bb1));
                    *reinterpret_cast<__half2*>(smc + H1_B + (ar + 8) * 256 +
                        (((gr) ^ arm) << 4) + bo) =
                        __floats2half2_rn(leaky(c1[t][nt][2] + bb0), leaky(c1[t][nt][3] + bb1));
                }
            }
        }
        __syncthreads();   // h1 visible

        // ================= layer 2: h2 = leaky(h1 @ W2_e + b2_e) ===============
        float c2[2][2][4];
#pragma unroll
        for (int t = 0; t < 2; t++)
#pragma unroll
            for (int i = 0; i < 2; i++)
#pragma unroll
                for (int jj = 0; jj < 4; jj++) c2[t][i][jj] = 0.f;

        for (int c = 0; c < 4; c++) {
            CP_WAIT0();
            __syncthreads();
            if (c >= 1 && c <= 2) {
                stage_lin(sb, W2BUF((c + 1) & 1), w2i + (c + 1) * 2048, 2048, tid);
                CP_COMMIT();
            }
            const uint32_t wb2 = sb + (uint32_t)W2BUF(c & 1) + boffB2;
#pragma unroll
            for (int s = 0; s < 2; s++) {
                const uint32_t sw = (uint32_t)((((c << 2) + (s << 1) + hi) ^ rm) << 4);
                uint32_t a0[4], a1[4];
                ldsm4(a0, h1Row0 + sw);
                ldsm4(a1, h1Row1 + sw);
                uint2 bp[2];
#pragma unroll
                for (int nt = 0; nt < 2; nt++)
                    bp[nt] = lds64(wb2 + (uint32_t)(s * 2048 + nt * 256));
#pragma unroll
                for (int nt = 0; nt < 2; nt++) {
                    mma16(c2[0][nt], a0[0], a0[1], a0[2], a0[3], bp[nt].x, bp[nt].y);
                    mma16(c2[1][nt], a1[0], a1[1], a1[2], a1[3], bp[nt].x, bp[nt].y);
                }
            }
        }
        __syncthreads();   // done reading W2 bufs + h1

        // Wg chunk 0 into h1 region (freed above) — overlaps h2 epilogue
        stage_lin(sb, WGBUF(0), wgi, 4096, tid);
        CP_COMMIT();

        // h2 epilogue -> h2 region (overwrites W2 staging)
        {
#pragma unroll
            for (int t = 0; t < 2; t++) {
                const int ar = mq * 32 + t * 16 + g;
                const int arm = ar & 7;
#pragma unroll
                for (int nt = 0; nt < 2; nt++) {
                    const int colb = ng * 16 + nt * 8 + 2 * tq;
                    const float bb0 = b2[e * H2D + colb];
                    const float bb1 = b2[e * H2D + colb + 1];
                    const int gr = colb >> 3;
                    const int bo = (colb & 7) * 2;
                    *reinterpret_cast<__half2*>(smc + H2_B + ar * 128 +
                        ((gr ^ arm) << 4) + bo) =
                        __floats2half2_rn(leaky(c2[t][nt][0] + bb0), leaky(c2[t][nt][1] + bb1));
                    *reinterpret_cast<__half2*>(smc + H2_B + (ar + 8) * 128 +
                        ((gr ^ arm) << 4) + bo) =
                        __floats2half2_rn(leaky(c2[t][nt][2] + bb0), leaky(c2[t][nt][3] + bb1));
                }
            }
        }

        // ====== gate GEMM (Wg chunks through h1 region) ========================
        float cg[2][4][4];
#pragma unroll
        for (int t = 0; t < 2; t++)
#pragma unroll
            for (int i = 0; i < 4; i++)
#pragma unroll
                for (int jj = 0; jj < 4; jj++) cg[t][i][jj] = 0.f;

        for (int c = 0; c < 8; c++) {
            CP_WAIT0();
            __syncthreads();
            if (c < 7) {
                stage_lin(sb, WGBUF((c + 1) & 1), wgi + (c + 1) * 4096, 4096, tid);
                CP_COMMIT();
            } else {
                // WGBUF(0) free (last read at c==6, fenced by this iter's sync):
                // start W3 chunk 0 while computing the final gate chunk
                stage_lin(sb, W3BUF, w3i, 4096, tid);
                CP_COMMIT();
            }
            const uint32_t wbg = sb + (uint32_t)WGBUF(c & 1) + boffB;
#pragma unroll
            for (int s = 0; s < 2; s++) {
                const uint32_t sw = (uint32_t)((((c << 2) + (s << 1) + hi) ^ rm) << 4);
                uint32_t a0[4], a1[4];
                ldsm4(a0, xRow0 + sw);
                ldsm4(a1, xRow1 + sw);
                uint2 bp[4];
#pragma unroll
                for (int nt = 0; nt < 4; nt++)
                    bp[nt] = lds64(wbg + (uint32_t)(s * 4096 + nt * 256));
#pragma unroll
                for (int nt = 0; nt < 4; nt++) {
                    mma16(cg[0][nt], a0[0], a0[1], a0[2], a0[3], bp[nt].x, bp[nt].y);
                    mma16(cg[1][nt], a1[0], a1[1], a1[2], a1[3], bp[nt].x, bp[nt].y);
                }
            }
        }
        __syncthreads();   // all warps done reading WGBUF(1)

        // W3 chunk 1 (chunk 0 already in flight)
        stage_lin(sb, W3BUF + 8192, w3i + 4096, 4096, tid);
        CP_COMMIT();
        CP_WAIT0();
        __syncthreads();   // W3 fully visible

        // ====== layer 3 + fold, per m-tile =====================================
        const uint32_t w3base = sb + (uint32_t)W3BUF + boffB;
#pragma unroll 1
        for (int t = 0; t < 2; t++) {
            float co[4][4];
#pragma unroll
            for (int i = 0; i < 4; i++)
#pragma unroll
                for (int jj = 0; jj < 4; jj++) co[i][jj] = 0.f;

            const uint32_t hRow = t ? h2Row1 : h2Row0;
#pragma unroll
            for (int ks = 0; ks < 4; ks++) {
                const uint32_t sw = (uint32_t)((((ks << 1) + hi) ^ rm) << 4);
                uint32_t a[4];
                ldsm4(a, hRow + sw);
                uint2 bp[4];
#pragma unroll
                for (int nt = 0; nt < 4; nt++)
                    bp[nt] = lds64(w3base + (uint32_t)(ks * 4096 + nt * 256));
#pragma unroll
                for (int nt = 0; nt < 4; nt++)
                    mma16(co[nt], a[0], a[1], a[2], a[3], bp[nt].x, bp[nt].y);
            }
            // fold: acc += exp(gate)*(o+b3); ssum += exp(gate)
#pragma unroll
            for (int nt = 0; nt < 4; nt++) {
                const int colc = octa + ng * 32 + nt * 8 + 2 * tq;
                const float bg0 = bg[e * ODIM + colc];
                const float bg1 = bg[e * ODIM + colc + 1];
                const float b30 = b3[e * ODIM + colc];
                const float b31 = b3[e * ODIM + colc + 1];
                const int ai = t * 4 + nt;
                float p;
                p = __expf(cg[t][nt][0] + bg0); acc[ai][0] += p * (co[nt][0] + b30); ssum[ai][0] += p;
                p = __expf(cg[t][nt][1] + bg1); acc[ai][1] += p * (co[nt][1] + b31); ssum[ai][1] += p;
                p = __expf(cg[t][nt][2] + bg0); acc[ai][2] += p * (co[nt][2] + b30); ssum[ai][2] += p;
                p = __expf(cg[t][nt][3] + bg1); acc[ai][3] += p * (co[nt][3] + b31); ssum[ai][3] += p;
            }
        }
        // expert-top S0 guards h1(W3)/h2 region reuse
    }

    // ---- epilogue: out = acc / ssum ----
#pragma unroll
    for (int ai = 0; ai < 8; ai++) {
        const int t = ai >> 2, nt = ai & 3;
        const int colc = octa + ng * 32 + nt * 8 + 2 * tq;
        const int ar = mq * 32 + t * 16 + g;
        const size_t r0 = (size_t)(row0 + ar) * ODIM;
        const size_t r1 = (size_t)(row0 + ar + 8) * ODIM;
        float2 v0 = make_float2(acc[ai][0] / ssum[ai][0], acc[ai][1] / ssum[ai][1]);
        float2 v1 = make_float2(acc[ai][2] / ssum[ai][2], acc[ai][3] / ssum[ai][3]);
        *reinterpret_cast<float2*>(out + r0 + colc) = v0;
        *reinterpret_cast<float2*>(out + r1 + colc) = v1;
    }
}

extern "C" void kernel_launch(void* const* d_in, const int* in_sizes, int n_in,
                              void* d_out, int out_size) {
    const float* x  = (const float*)d_in[0];
    const float* W1 = (const float*)d_in[1];
    const float* b1 = (const float*)d_in[2];
    const float* W2 = (const float*)d_in[3];
    const float* b2 = (const float*)d_in[4];
    const float* W3 = (const float*)d_in[5];
    const float* b3 = (const float*)d_in[6];
    const float* Wg = (const float*)d_in[7];
    const float* bg = (const float*)d_in[8];
    float* out = (float*)d_out;
    (void)n_in; (void)out_size;

    const int B  = in_sizes[0] / LDIM;       // 65536
    const int nb = (B / BT) * 2;             // 2048 CTAs

    prep_weights<<<256, 256>>>(W1, W2, W3, Wg);

    cudaFuncSetAttribute(moe_fused_kernel,
                         cudaFuncAttributeMaxDynamicSharedMemorySize, SMEM_BYTES);
    moe_fused_kernel<<<nb, NTHREADS, SMEM_BYTES>>>(x, b1, b2, b3, bg, out);
}